// round 1
// baseline (speedup 1.0000x reference)
#include <cuda_runtime.h>
#include <math.h>

#define NB 16
#define NH 32
#define NKVH 8
#define ND 128
#define NS 4096
#define NG 4
#define NSPLIT 32
#define CHUNK (NS / NSPLIT)   // 128
#define TILE 64
#define ATT_SCALE 0.08838834764831845f   // 1/sqrt(128)

// Split-KV partial results (static device scratch — no allocation allowed).
__device__ float g_acc[(size_t)NB * NH * NSPLIT * ND];  // 8 MB
__device__ float g_m[NB * NH * NSPLIT];
__device__ float g_l[NB * NH * NSPLIT];

__device__ __forceinline__ void process_key(
    float4 cc, float2 kA, float2 kB, float4 vv,
    const float* qlx, const float* qly, const float* qhx, const float* qhy,
    float* m, float* l, float4* acc)
{
    // RoPE on K: lane owns dims (2l, 2l+1, 2l+64, 2l+65); pair is lane-local.
    float r0 = kA.x * cc.x - kB.x * cc.z;
    float r1 = kA.y * cc.y - kB.y * cc.w;
    float r2 = kB.x * cc.x + kA.x * cc.z;
    float r3 = kB.y * cc.y + kA.y * cc.w;

    float d[NG];
#pragma unroll
    for (int g = 0; g < NG; g++)
        d[g] = qlx[g] * r0 + qly[g] * r1 + qhx[g] * r2 + qhy[g] * r3;

    // Full-warp butterfly: every lane ends with the complete dot for all 4 heads.
#pragma unroll
    for (int o = 16; o > 0; o >>= 1) {
#pragma unroll
        for (int g = 0; g < NG; g++)
            d[g] += __shfl_xor_sync(0xffffffffu, d[g], o);
    }

#pragma unroll
    for (int g = 0; g < NG; g++) {
        float sc = d[g] * ATT_SCALE;
        if (sc > m[g]) {                    // rare (≈log n times), warp-uniform
            float corr = __expf(m[g] - sc);
            m[g] = sc;
            l[g] *= corr;
            acc[g].x *= corr; acc[g].y *= corr;
            acc[g].z *= corr; acc[g].w *= corr;
        }
        float wgt = __expf(sc - m[g]);
        l[g] += wgt;
        acc[g].x = fmaf(wgt, vv.x, acc[g].x);
        acc[g].y = fmaf(wgt, vv.y, acc[g].y);
        acc[g].z = fmaf(wgt, vv.z, acc[g].z);
        acc[g].w = fmaf(wgt, vv.w, acc[g].w);
    }
}

__global__ __launch_bounds__(256, 2)
void pa_partial_kernel(const float* __restrict__ query,
                       const float* __restrict__ k_cache,
                       const float* __restrict__ v_cache,
                       const int*   __restrict__ slots,
                       const int*   __restrict__ positions,
                       const int*   __restrict__ ctx_lens)
{
    __shared__ float4 cs[TILE][32];   // (c0,c1,s0,s1) per (key, lane-pair): 32 KB
    __shared__ int    slot_sh[TILE];

    const int split = blockIdx.x;
    const int b     = blockIdx.y;
    const int tid   = threadIdx.x;
    const int w     = tid >> 5;       // warp = kv head
    const int lane  = tid & 31;

    const int ctx     = ctx_lens[b];
    const int s_begin = split * CHUNK;
    const int s_end   = min(ctx, s_begin + CHUNK);

    // inv_freq for this lane's frequency pair (indices 2l, 2l+1), fp64 init.
    const float inv0 = (float)exp(-9.210340371976184 * (double)(2 * lane)     / 64.0);
    const float inv1 = (float)exp(-9.210340371976184 * (double)(2 * lane + 1) / 64.0);

    // ---- RoPE'd query (pos_last), 4 heads, kept in registers ----
    float qlx[NG], qly[NG], qhx[NG], qhy[NG];
    {
        const int pos_last = positions[b * NS + ctx - 1];
        float sn0, cn0, sn1, cn1;
        sincosf((float)pos_last * inv0, &sn0, &cn0);
        sincosf((float)pos_last * inv1, &sn1, &cn1);
#pragma unroll
        for (int g = 0; g < NG; g++) {
            const float* qp = query + (size_t)(b * NH + w * NG + g) * ND;
            float2 a  = *(const float2*)(qp + 2 * lane);
            float2 bb = *(const float2*)(qp + 2 * lane + 64);
            qlx[g] = a.x * cn0 - bb.x * sn0;
            qly[g] = a.y * cn1 - bb.y * sn1;
            qhx[g] = bb.x * cn0 + a.x * sn0;
            qhy[g] = bb.y * cn1 + a.y * sn1;
        }
    }

    float  m[NG], l[NG];
    float4 acc[NG];
#pragma unroll
    for (int g = 0; g < NG; g++) {
        m[g] = -1e30f; l[g] = 0.f;
        acc[g] = make_float4(0.f, 0.f, 0.f, 0.f);
    }

    const float* kb = k_cache + w * ND;
    const float* vb = v_cache + w * ND;

    for (int t0 = s_begin; t0 < s_end; t0 += TILE) {
        const int n = min(TILE, s_end - t0);
        __syncthreads();   // previous tile fully consumed before refill
        if (tid < n) slot_sh[tid] = slots[b * NS + t0 + tid];
        // cos/sin computed ONCE per (b,s), shared by all 8 kv-head warps.
        for (int key = w; key < n; key += 8) {
            float p = (float)positions[b * NS + t0 + key];
            float fs0, fc0, fs1, fc1;
            sincosf(p * inv0, &fs0, &fc0);
            sincosf(p * inv1, &fs1, &fc1);
            cs[key][lane] = make_float4(fc0, fc1, fs0, fs1);
        }
        __syncthreads();

#define LOADK(j, KA, KB, VV)                                            \
        {                                                               \
            int sl_ = slot_sh[(j)];                                     \
            const float* kr_ = kb + (size_t)sl_ * (NKVH * ND);          \
            const float* vr_ = vb + (size_t)sl_ * (NKVH * ND);          \
            KA = *(const float2*)(kr_ + 2 * lane);                      \
            KB = *(const float2*)(kr_ + 2 * lane + 64);                 \
            VV = *(const float4*)(vr_ + 4 * lane);                      \
        }

        // depth-2 software pipeline: K/V for key i+2 in flight while
        // processing key i → ~2 KB outstanding per warp.
        float2 kA0, kB0, kA1, kB1;
        float4 v0, v1;
        LOADK(0, kA0, kB0, v0);
        {
            int j1 = min(1, n - 1);
            LOADK(j1, kA1, kB1, v1);
        }
        for (int i = 0; i < n; i += 2) {
            {
                float2 ka = kA0, kk = kB0; float4 vv = v0;
                int j = min(i + 2, n - 1);
                LOADK(j, kA0, kB0, v0);
                process_key(cs[i][lane], ka, kk, vv, qlx, qly, qhx, qhy, m, l, acc);
            }
            if (i + 1 < n) {
                float2 ka = kA1, kk = kB1; float4 vv = v1;
                int j = min(i + 3, n - 1);
                LOADK(j, kA1, kB1, v1);
                process_key(cs[i + 1][lane], ka, kk, vv, qlx, qly, qhx, qhy, m, l, acc);
            }
        }
#undef LOADK
    }

    // ---- write split partials ----
#pragma unroll
    for (int g = 0; g < NG; g++) {
        int h = w * NG + g;
        size_t p = (size_t)(b * NH + h) * NSPLIT + split;
        if (s_end > s_begin)
            *(float4*)(g_acc + p * ND + 4 * lane) = acc[g];
        if (lane == 0) { g_m[p] = m[g]; g_l[p] = l[g]; }
    }
}

__global__ void pa_combine_kernel(float* __restrict__ out)
{
    const int bh = blockIdx.x;      // b*NH + h
    const int d  = threadIdx.x;     // 0..127

    const float* mrow = g_m + (size_t)bh * NSPLIT;
    const float* lrow = g_l + (size_t)bh * NSPLIT;

    float mv[NSPLIT];
    float M = -1e30f;
#pragma unroll
    for (int s = 0; s < NSPLIT; s++) { mv[s] = mrow[s]; M = fmaxf(M, mv[s]); }

    float L = 0.f, o = 0.f;
#pragma unroll
    for (int s = 0; s < NSPLIT; s++) {
        float f = __expf(mv[s] - M);           // exactly 0 for empty splits
        L += f * lrow[s];
        o += f * g_acc[((size_t)bh * NSPLIT + s) * ND + d];
    }
    out[(size_t)bh * ND + d] = o / L;
}

extern "C" void kernel_launch(void* const* d_in, const int* in_sizes, int n_in,
                              void* d_out, int out_size)
{
    const float* query     = (const float*)d_in[0];
    const float* k_cache   = (const float*)d_in[1];
    const float* v_cache   = (const float*)d_in[2];
    const int*   slots     = (const int*)d_in[3];
    const int*   positions = (const int*)d_in[4];
    const int*   ctx_lens  = (const int*)d_in[5];
    float*       out       = (float*)d_out;

    dim3 grid(NSPLIT, NB);
    pa_partial_kernel<<<grid, 256>>>(query, k_cache, v_cache, slots, positions, ctx_lens);
    pa_combine_kernel<<<NB * NH, ND>>>(out);
}